// round 3
// baseline (speedup 1.0000x reference)
#include <cuda_runtime.h>
#include <math.h>

#define BB 8192
#define DD 1024
#define EE 8
#define NQv 8
#define NLv 2
#define HHv 1024

// ---------------- scratch (static device globals: no allocation) ----------------
__device__ float g_X1[(size_t)BB * DD];        // inter-block activations (32MB)
__device__ float g_H[(size_t)BB * 2 * HHv];    // gated, scaled hidden per (row,slot) (64MB)
__device__ float g_OUT[(size_t)BB * DD];       // residual + bias + GEMM accumulator (32MB)
__device__ int   g_cnt[EE];
__device__ int   g_list[EE * BB];              // entries encode row*2+slot

// ---------------- reset ----------------
__global__ void k_reset() {
    if (threadIdx.x < EE) g_cnt[threadIdx.x] = 0;
}

// ---------------- fused gate + qsim + hidden ----------------
__global__ __launch_bounds__(256) void k_gate_qsim(
    const float* __restrict__ Xext,
    const float* __restrict__ gW, const float* __restrict__ gb,
    const float* __restrict__ qp, const float* __restrict__ rW,
    const float* __restrict__ rb, const float* __restrict__ b2,
    int blk)
{
    __shared__ float xrow[DD];
    __shared__ float2 st[256];
    __shared__ float2 m00[NQv], m01[NQv], m10[NQv], m11[NQv];
    __shared__ float logits[EE];
    __shared__ float cq[NQv], sq[NQv];
    __shared__ float qv[2][NQv];
    __shared__ int   sel[2];
    __shared__ float wsel[2];

    const float* X = (blk == 0) ? Xext : g_X1;
    int b = blockIdx.x;
    int tid = threadIdx.x;

    const float* xr = X + (size_t)b * DD;
    for (int d = tid; d < DD; d += 256) xrow[d] = xr[d];
    if (tid < EE) logits[tid] = 0.f;
    if (tid < 2 * NQv) qv[tid >> 3][tid & 7] = 0.f;
    __syncthreads();

    // ---- gate logits ----
    float acc[EE];
    #pragma unroll
    for (int e = 0; e < EE; e++) acc[e] = 0.f;
    for (int d = tid; d < DD; d += 256) {
        float xv = xrow[d];
        const float* gwr = gW + ((size_t)blk * DD + d) * EE;
        #pragma unroll
        for (int e = 0; e < EE; e++) acc[e] += xv * gwr[e];
    }
    #pragma unroll
    for (int e = 0; e < EE; e++) {
        float v = acc[e];
        #pragma unroll
        for (int o = 16; o > 0; o >>= 1) v += __shfl_xor_sync(0xffffffffu, v, o);
        if ((tid & 31) == 0) atomicAdd(&logits[e], v);
    }
    __syncthreads();

    if (tid == 0) {
        float l[EE], mx = -1e30f;
        #pragma unroll
        for (int e = 0; e < EE; e++) { l[e] = logits[e] + gb[blk * EE + e]; mx = fmaxf(mx, l[e]); }
        float sum = 0.f;
        #pragma unroll
        for (int e = 0; e < EE; e++) { l[e] = expf(l[e] - mx); sum += l[e]; }
        float inv = 1.f / sum;
        #pragma unroll
        for (int e = 0; e < EE; e++) l[e] *= inv;
        // top-2, first-occurrence tie-break (matches lax.top_k)
        int i0 = 0;
        #pragma unroll
        for (int e = 1; e < EE; e++) if (l[e] > l[i0]) i0 = e;
        int i1 = (i0 == 0) ? 1 : 0;
        #pragma unroll
        for (int e = 0; e < EE; e++) if (e != i1 && e != i0 && l[e] > l[i1]) i1 = e;
        float p0 = l[i0], p1 = l[i1];
        // softmax over the two (already-softmaxed) probabilities — exact per reference
        float w1 = 1.f / (1.f + expf(p0 - p1));
        float w0 = 1.f - w1;
        sel[0] = i0; sel[1] = i1; wsel[0] = w0; wsel[1] = w1;
        int pos0 = atomicAdd(&g_cnt[i0], 1); g_list[i0 * BB + pos0] = b * 2 + 0;
        int pos1 = atomicAdd(&g_cnt[i1], 1); g_list[i1 * BB + pos1] = b * 2 + 1;
    }
    if (tid < NQv) {
        float a = 0.5f * xrow[tid];
        cq[tid] = cosf(a);
        sq[tid] = sinf(a);
    }
    __syncthreads();

    // ---- init accumulator: residual + weighted expert biases ----
    {
        int e0 = sel[0], e1 = sel[1];
        float w0 = wsel[0], w1 = wsel[1];
        const float* b2a = b2 + ((size_t)blk * EE + e0) * DD;
        const float* b2b = b2 + ((size_t)blk * EE + e1) * DD;
        for (int n = tid; n < DD; n += 256)
            g_OUT[(size_t)b * DD + n] = xrow[n] + w0 * b2a[n] + w1 * b2b[n];
    }

    // ---- quantum sim per selected expert ----
    for (int s = 0; s < 2; s++) {
        int e = sel[s];
        // initial product state (real)
        {
            float v = 1.f;
            #pragma unroll
            for (int q = 0; q < NQv; q++)
                v *= ((tid >> (NQv - 1 - q)) & 1) ? sq[q] : cq[q];
            st[tid] = make_float2(v, 0.f);
        }
        const float* qpe = qp + ((size_t)(blk * EE + e) * NLv) * NQv * 3;
        for (int l = 0; l < NLv; l++) {
            __syncthreads();
            if (tid < NQv) {
                const float* p = qpe + (l * NQv + tid) * 3;
                float phi = p[0], th = p[1], om = p[2];
                float c, sn; sincosf(0.5f * th, &sn, &c);
                float sa, ca; sincosf(0.5f * (phi + om), &sa, &ca);
                float sb, cb; sincosf(0.5f * (phi - om), &sb, &cb);
                m00[tid] = make_float2(ca * c, -sa * c);
                m11[tid] = make_float2(ca * c,  sa * c);
                m01[tid] = make_float2(-cb * sn, -sb * sn);
                m10[tid] = make_float2( cb * sn, -sb * sn);
            }
            __syncthreads();
            #pragma unroll
            for (int q = 0; q < NQv; q++) {
                int pb = NQv - 1 - q;
                if (tid < 128) {
                    int i0 = ((tid >> pb) << (pb + 1)) | (tid & ((1 << pb) - 1));
                    int i1 = i0 | (1 << pb);
                    float2 a0 = st[i0], a1 = st[i1];
                    float2 M00 = m00[q], M01 = m01[q], M10 = m10[q], M11 = m11[q];
                    float2 n0, n1;
                    n0.x = M00.x * a0.x - M00.y * a0.y + M01.x * a1.x - M01.y * a1.y;
                    n0.y = M00.x * a0.y + M00.y * a0.x + M01.x * a1.y + M01.y * a1.x;
                    n1.x = M10.x * a0.x - M10.y * a0.y + M11.x * a1.x - M11.y * a1.y;
                    n1.y = M10.x * a0.y + M10.y * a0.x + M11.x * a1.y + M11.y * a1.x;
                    st[i0] = n0; st[i1] = n1;
                }
                __syncthreads();
            }
            // CNOT chain q=0..6 collapsed into one permutation:
            // source(i) = sigma_{0,1}(sigma_{1,2}(...sigma_{6,7}(i)))
            {
                int j = tid;
                #pragma unroll
                for (int q = NQv - 2; q >= 0; q--) {
                    int pc = NQv - 1 - q;      // control bit position
                    int pt = NQv - 2 - q;      // target bit position
                    j ^= ((j >> pc) & 1) << pt;
                }
                float2 v = st[j];
                __syncthreads();
                st[tid] = v;
            }
        }
        __syncthreads();
        // Z expectations
        {
            float p = st[tid].x * st[tid].x + st[tid].y * st[tid].y;
            #pragma unroll
            for (int k = 0; k < NQv; k++) {
                float v = ((tid >> (NQv - 1 - k)) & 1) ? -p : p;
                #pragma unroll
                for (int o = 16; o > 0; o >>= 1) v += __shfl_xor_sync(0xffffffffu, v, o);
                if ((tid & 31) == 0) atomicAdd(&qv[s][k], v);
            }
        }
        __syncthreads();
    }

    // ---- hidden: h = relu(q @ rW + rb) * gate_weight ----
    #pragma unroll
    for (int s = 0; s < 2; s++) {
        int e = sel[s];
        float w = wsel[s];
        float qr[NQv];
        #pragma unroll
        for (int j = 0; j < NQv; j++) qr[j] = qv[s][j];
        const float* rWe = rW + ((size_t)(blk * EE + e)) * NQv * HHv;
        const float* rbe = rb + ((size_t)(blk * EE + e)) * HHv;
        float* Hd = g_H + ((size_t)b * 2 + s) * HHv;
        for (int n = tid; n < HHv; n += 256) {
            float a = rbe[n];
            #pragma unroll
            for (int j = 0; j < NQv; j++) a += qr[j] * rWe[j * HHv + n];
            Hd[n] = fmaxf(a, 0.f) * w;
        }
    }
}

// ---------------- grouped expert GEMM: OUT += H_gathered @ w2[e] ----------------
__global__ __launch_bounds__(256) void k_moe_gemm(const float* __restrict__ w2, int blk)
{
    int e = blockIdx.z;
    int n_e = g_cnt[e];
    int m0 = blockIdx.y * 64;
    if (m0 >= n_e) return;
    int n0 = blockIdx.x * 64;

    __shared__ float As[16][68];
    __shared__ float Bs[16][64];
    __shared__ int   rows[64];

    int tid = threadIdx.x;
    if (tid < 64) {
        int m = m0 + tid;
        rows[tid] = (m < n_e) ? g_list[e * BB + m] : -1;
    }
    __syncthreads();

    const float* w2e = w2 + ((size_t)(blk * EE + e)) * HHv * DD;

    float accum[4][4];
    #pragma unroll
    for (int i = 0; i < 4; i++)
        #pragma unroll
        for (int j = 0; j < 4; j++) accum[i][j] = 0.f;

    int tr = (tid >> 4) * 4;
    int tc = (tid & 15) * 4;
    int la_m = tid >> 2;
    int la_k = (tid & 3) * 4;
    int lb_k = tid >> 4;
    int lb_n = (tid & 15) * 4;

    int rowA = rows[la_m];
    const float* Hrow = (rowA >= 0) ? (g_H + (size_t)rowA * HHv) : 0;

    for (int k0 = 0; k0 < HHv; k0 += 16) {
        float4 av = Hrow ? *(const float4*)(Hrow + k0 + la_k) : make_float4(0.f, 0.f, 0.f, 0.f);
        float4 bv = *(const float4*)(w2e + (size_t)(k0 + lb_k) * DD + n0 + lb_n);
        __syncthreads();
        As[la_k + 0][la_m] = av.x;
        As[la_k + 1][la_m] = av.y;
        As[la_k + 2][la_m] = av.z;
        As[la_k + 3][la_m] = av.w;
        *(float4*)&Bs[lb_k][lb_n] = bv;
        __syncthreads();
        #pragma unroll
        for (int k = 0; k < 16; k++) {
            float a0 = As[k][tr], a1 = As[k][tr + 1], a2 = As[k][tr + 2], a3 = As[k][tr + 3];
            float4 bq = *(float4*)&Bs[k][tc];
            accum[0][0] += a0 * bq.x; accum[0][1] += a0 * bq.y; accum[0][2] += a0 * bq.z; accum[0][3] += a0 * bq.w;
            accum[1][0] += a1 * bq.x; accum[1][1] += a1 * bq.y; accum[1][2] += a1 * bq.z; accum[1][3] += a1 * bq.w;
            accum[2][0] += a2 * bq.x; accum[2][1] += a2 * bq.y; accum[2][2] += a2 * bq.z; accum[2][3] += a2 * bq.w;
            accum[3][0] += a3 * bq.x; accum[3][1] += a3 * bq.y; accum[3][2] += a3 * bq.z; accum[3][3] += a3 * bq.w;
        }
    }

    #pragma unroll
    for (int i = 0; i < 4; i++) {
        int rs = rows[tr + i];
        if (rs < 0) continue;
        float* outp = g_OUT + (size_t)(rs >> 1) * DD + n0 + tc;
        atomicAdd(outp + 0, accum[i][0]);
        atomicAdd(outp + 1, accum[i][1]);
        atomicAdd(outp + 2, accum[i][2]);
        atomicAdd(outp + 3, accum[i][3]);
    }
}

// ---------------- layernorm ----------------
__device__ __forceinline__ float blockReduceSum(float v, float* red)
{
    __syncthreads();
    int lane = threadIdx.x & 31;
    int w = threadIdx.x >> 5;
    #pragma unroll
    for (int o = 16; o > 0; o >>= 1) v += __shfl_xor_sync(0xffffffffu, v, o);
    if (lane == 0) red[w] = v;
    __syncthreads();
    float r = (lane < 8) ? red[lane] : 0.f;
    #pragma unroll
    for (int o = 4; o > 0; o >>= 1) r += __shfl_xor_sync(0xffffffffu, r, o);
    return r;  // valid in lane groups; broadcast below
}

__global__ __launch_bounds__(256) void k_ln(
    const float* __restrict__ gam, const float* __restrict__ bet,
    float* __restrict__ Yext, int blk)
{
    __shared__ float red[32];
    __shared__ float bc[2];
    int b = blockIdx.x, tid = threadIdx.x;
    float* Y = (blk == 0) ? g_X1 : Yext;

    const float* y = g_OUT + (size_t)b * DD;
    float v[4];
    float s = 0.f;
    #pragma unroll
    for (int i = 0; i < 4; i++) { v[i] = y[tid + 256 * i]; s += v[i]; }
    float tot = blockReduceSum(s, red);
    if (tid == 0) bc[0] = tot;
    __syncthreads();
    float mu = bc[0] * (1.f / 1024.f);

    float s2 = 0.f;
    #pragma unroll
    for (int i = 0; i < 4; i++) { float d = v[i] - mu; s2 += d * d; }
    float tot2 = blockReduceSum(s2, red);
    if (tid == 0) bc[1] = tot2;
    __syncthreads();
    float inv = 1.f / sqrtf(bc[1] * (1.f / 1024.f) + 1e-5f);

    #pragma unroll
    for (int i = 0; i < 4; i++) {
        int n = tid + 256 * i;
        Y[(size_t)b * DD + n] = (v[i] - mu) * inv * gam[blk * DD + n] + bet[blk * DD + n];
    }
}

// ---------------- launch ----------------
extern "C" void kernel_launch(void* const* d_in, const int* in_sizes, int n_in,
                              void* d_out, int out_size)
{
    (void)in_sizes; (void)n_in; (void)out_size;
    const float* x  = (const float*)d_in[0];
    const float* gW = (const float*)d_in[1];
    const float* gb = (const float*)d_in[2];
    const float* qp = (const float*)d_in[3];
    const float* rW = (const float*)d_in[4];
    const float* rb = (const float*)d_in[5];
    const float* w2 = (const float*)d_in[6];
    const float* b2 = (const float*)d_in[7];
    const float* lg = (const float*)d_in[8];
    const float* lb = (const float*)d_in[9];
    float* out = (float*)d_out;

    for (int blk = 0; blk < 2; blk++) {
        k_reset<<<1, 32>>>();
        k_gate_qsim<<<BB, 256>>>(x, gW, gb, qp, rW, rb, b2, blk);
        dim3 g2(DD / 64, BB / 64, EE);
        k_moe_gemm<<<g2, 256>>>(w2, blk);
        k_ln<<<BB, 256>>>(lg, lb, out, blk);
    }
}

// round 6
// speedup vs baseline: 2.0303x; 2.0303x over previous
#include <cuda_runtime.h>
#include <cuda_bf16.h>
#include <cstdint>
#include <math.h>

#define BB 8192
#define DD 1024
#define EE 8
#define NQv 8
#define NLv 2
#define HHv 1024

// ---------------- scratch (static device globals: no allocation) ----------------
__device__ float g_X1[(size_t)BB * DD];                 // inter-block activations
__device__ __nv_bfloat16 g_Hhi[(size_t)BB * 2 * HHv];   // hidden, bf16 hi
__device__ __nv_bfloat16 g_Hlo[(size_t)BB * 2 * HHv];   // hidden, bf16 lo
__device__ float g_OUT[(size_t)BB * DD];                // residual + expert biases
__device__ float g_Eout[(size_t)BB * 2 * DD];           // per-slot GEMM output
__device__ __nv_bfloat16 g_w2Thi[(size_t)2 * EE * DD * HHv]; // w2^T [e][n][k] hi
__device__ __nv_bfloat16 g_w2Tlo[(size_t)2 * EE * DD * HHv]; // w2^T [e][n][k] lo
__device__ int   g_cnt[EE];
__device__ int   g_list[EE * BB];                       // entries encode row*2+slot

// ---------------- generic PTX helpers (no sm_103a-only instructions!) ----------------
static __device__ __forceinline__ uint32_t smem_u32(const void* p) {
    uint32_t a;
    asm("{ .reg .u64 t; cvta.to.shared.u64 t, %1; cvt.u32.u64 %0, t; }" : "=r"(a) : "l"(p));
    return a;
}
static __device__ __forceinline__ void cp16(uint32_t dst, const void* src) {
    asm volatile("cp.async.cg.shared.global [%0], [%1], 16;" :: "r"(dst), "l"(src) : "memory");
}
static __device__ __forceinline__ void cp16z(uint32_t dst, const void* src, int srcsize) {
    asm volatile("cp.async.cg.shared.global [%0], [%1], 16, %2;" :: "r"(dst), "l"(src), "r"(srcsize) : "memory");
}
static __device__ __forceinline__ void cp_commit() {
    asm volatile("cp.async.commit_group;" ::: "memory");
}
static __device__ __forceinline__ void ldm4(uint32_t* r, uint32_t addr) {
    asm volatile("ldmatrix.sync.aligned.m8n8.x4.shared.b16 {%0,%1,%2,%3}, [%4];"
        : "=r"(r[0]), "=r"(r[1]), "=r"(r[2]), "=r"(r[3]) : "r"(addr));
}
static __device__ __forceinline__ void mma16816(float* c, const uint32_t* a, const uint32_t* b) {
    asm volatile("mma.sync.aligned.m16n8k16.row.col.f32.bf16.bf16.f32 "
        "{%0,%1,%2,%3}, {%4,%5,%6,%7}, {%8,%9}, {%0,%1,%2,%3};"
        : "+f"(c[0]), "+f"(c[1]), "+f"(c[2]), "+f"(c[3])
        : "r"(a[0]), "r"(a[1]), "r"(a[2]), "r"(a[3]), "r"(b[0]), "r"(b[1]));
}

// ---------------- GEMM tile config ----------------
#define BM 128
#define BN 128
#define BK 64
#define NCH (HHv / BK)                // 16
#define APAD 72                        // row stride in bf16 elements (144B: conflict-free)
#define TILE_BYT (BM * APAD * 2)       // 18432 bytes per tile
#define STAGE_BYT (4 * TILE_BYT)       // Ahi, Alo, Bhi, Blo
#define GEMM_SMEM (2 * STAGE_BYT)      // 147456 bytes

// ---------------- reset ----------------
__global__ void k_reset() {
    if (threadIdx.x < EE) g_cnt[threadIdx.x] = 0;
}

// ---------------- w2 -> w2^T, split fp32 into bf16 hi/lo ----------------
__global__ __launch_bounds__(256) void k_w2t(const float* __restrict__ w2)
{
    __shared__ float tile[32][33];
    int ez = blockIdx.z;
    int k0 = blockIdx.y * 32;
    int n0 = blockIdx.x * 32;
    int tx = threadIdx.x & 31, ty = threadIdx.x >> 5;

    const float* src = w2 + (size_t)ez * HHv * DD;
    #pragma unroll
    for (int r = 0; r < 32; r += 8)
        tile[ty + r][tx] = src[(size_t)(k0 + ty + r) * DD + n0 + tx];
    __syncthreads();

    __nv_bfloat16* dhi = g_w2Thi + (size_t)ez * DD * HHv;
    __nv_bfloat16* dlo = g_w2Tlo + (size_t)ez * DD * HHv;
    #pragma unroll
    for (int r = 0; r < 32; r += 8) {
        float v = tile[tx][ty + r];
        __nv_bfloat16 hi = __float2bfloat16(v);
        __nv_bfloat16 lo = __float2bfloat16(v - __bfloat162float(hi));
        size_t o = (size_t)(n0 + ty + r) * HHv + k0 + tx;
        dhi[o] = hi; dlo[o] = lo;
    }
}

// ---------------- fused gate + qsim + hidden ----------------
__global__ __launch_bounds__(256) void k_gate_qsim(
    const float* __restrict__ Xext,
    const float* __restrict__ gW, const float* __restrict__ gb,
    const float* __restrict__ qp, const float* __restrict__ rW,
    const float* __restrict__ rb, const float* __restrict__ b2,
    int blk)
{
    __shared__ float xrow[DD];
    __shared__ float2 st[256];
    __shared__ float2 m00[NQv], m01[NQv], m10[NQv], m11[NQv];
    __shared__ float logits[EE];
    __shared__ float cq[NQv], sq[NQv];
    __shared__ float qv[2][NQv];
    __shared__ int   sel[2];
    __shared__ float wsel[2];

    const float* X = (blk == 0) ? Xext : g_X1;
    int b = blockIdx.x;
    int tid = threadIdx.x;

    const float* xr = X + (size_t)b * DD;
    for (int d = tid; d < DD; d += 256) xrow[d] = xr[d];
    if (tid < EE) logits[tid] = 0.f;
    if (tid < 2 * NQv) qv[tid >> 3][tid & 7] = 0.f;
    __syncthreads();

    // ---- gate logits ----
    float acc[EE];
    #pragma unroll
    for (int e = 0; e < EE; e++) acc[e] = 0.f;
    for (int d = tid; d < DD; d += 256) {
        float xv = xrow[d];
        const float* gwr = gW + ((size_t)blk * DD + d) * EE;
        #pragma unroll
        for (int e = 0; e < EE; e++) acc[e] += xv * gwr[e];
    }
    #pragma unroll
    for (int e = 0; e < EE; e++) {
        float v = acc[e];
        #pragma unroll
        for (int o = 16; o > 0; o >>= 1) v += __shfl_xor_sync(0xffffffffu, v, o);
        if ((tid & 31) == 0) atomicAdd(&logits[e], v);
    }
    __syncthreads();

    if (tid == 0) {
        float l[EE], mx = -1e30f;
        #pragma unroll
        for (int e = 0; e < EE; e++) { l[e] = logits[e] + gb[blk * EE + e]; mx = fmaxf(mx, l[e]); }
        float sum = 0.f;
        #pragma unroll
        for (int e = 0; e < EE; e++) { l[e] = expf(l[e] - mx); sum += l[e]; }
        float inv = 1.f / sum;
        #pragma unroll
        for (int e = 0; e < EE; e++) l[e] *= inv;
        int i0 = 0;
        #pragma unroll
        for (int e = 1; e < EE; e++) if (l[e] > l[i0]) i0 = e;
        int i1 = (i0 == 0) ? 1 : 0;
        #pragma unroll
        for (int e = 0; e < EE; e++) if (e != i1 && e != i0 && l[e] > l[i1]) i1 = e;
        float p0 = l[i0], p1 = l[i1];
        float w1 = 1.f / (1.f + expf(p0 - p1));
        float w0 = 1.f - w1;
        sel[0] = i0; sel[1] = i1; wsel[0] = w0; wsel[1] = w1;
        int pos0 = atomicAdd(&g_cnt[i0], 1); g_list[i0 * BB + pos0] = b * 2 + 0;
        int pos1 = atomicAdd(&g_cnt[i1], 1); g_list[i1 * BB + pos1] = b * 2 + 1;
    }
    if (tid < NQv) {
        float a = 0.5f * xrow[tid];
        cq[tid] = cosf(a);
        sq[tid] = sinf(a);
    }
    __syncthreads();

    // ---- init accumulator: residual + weighted expert biases ----
    {
        int e0 = sel[0], e1 = sel[1];
        float w0 = wsel[0], w1 = wsel[1];
        const float* b2a = b2 + ((size_t)blk * EE + e0) * DD;
        const float* b2b = b2 + ((size_t)blk * EE + e1) * DD;
        for (int n = tid; n < DD; n += 256)
            g_OUT[(size_t)b * DD + n] = xrow[n] + w0 * b2a[n] + w1 * b2b[n];
    }

    // ---- quantum sim per selected expert ----
    for (int s = 0; s < 2; s++) {
        int e = sel[s];
        {
            float v = 1.f;
            #pragma unroll
            for (int q = 0; q < NQv; q++)
                v *= ((tid >> (NQv - 1 - q)) & 1) ? sq[q] : cq[q];
            st[tid] = make_float2(v, 0.f);
        }
        const float* qpe = qp + ((size_t)(blk * EE + e) * NLv) * NQv * 3;
        for (int l = 0; l < NLv; l++) {
            __syncthreads();
            if (tid < NQv) {
                const float* p = qpe + (l * NQv + tid) * 3;
                float phi = p[0], th = p[1], om = p[2];
                float c, sn; sincosf(0.5f * th, &sn, &c);
                float sa, ca; sincosf(0.5f * (phi + om), &sa, &ca);
                float sb, cb; sincosf(0.5f * (phi - om), &sb, &cb);
                m00[tid] = make_float2(ca * c, -sa * c);
                m11[tid] = make_float2(ca * c,  sa * c);
                m01[tid] = make_float2(-cb * sn, -sb * sn);
                m10[tid] = make_float2( cb * sn, -sb * sn);
            }
            __syncthreads();
            #pragma unroll
            for (int q = 0; q < NQv; q++) {
                int pb = NQv - 1 - q;
                if (tid < 128) {
                    int i0 = ((tid >> pb) << (pb + 1)) | (tid & ((1 << pb) - 1));
                    int i1 = i0 | (1 << pb);
                    float2 a0 = st[i0], a1 = st[i1];
                    float2 M00 = m00[q], M01 = m01[q], M10 = m10[q], M11 = m11[q];
                    float2 n0, n1;
                    n0.x = M00.x * a0.x - M00.y * a0.y + M01.x * a1.x - M01.y * a1.y;
                    n0.y = M00.x * a0.y + M00.y * a0.x + M01.x * a1.y + M01.y * a1.x;
                    n1.x = M10.x * a0.x - M10.y * a0.y + M11.x * a1.x - M11.y * a1.y;
                    n1.y = M10.x * a0.y + M10.y * a0.x + M11.x * a1.y + M11.y * a1.x;
                    st[i0] = n0; st[i1] = n1;
                }
                __syncthreads();
            }
            {
                int j = tid;
                #pragma unroll
                for (int q = NQv - 2; q >= 0; q--) {
                    int pc = NQv - 1 - q;
                    int pt = NQv - 2 - q;
                    j ^= ((j >> pc) & 1) << pt;
                }
                float2 v = st[j];
                __syncthreads();
                st[tid] = v;
            }
        }
        __syncthreads();
        {
            float p = st[tid].x * st[tid].x + st[tid].y * st[tid].y;
            #pragma unroll
            for (int k = 0; k < NQv; k++) {
                float v = ((tid >> (NQv - 1 - k)) & 1) ? -p : p;
                #pragma unroll
                for (int o = 16; o > 0; o >>= 1) v += __shfl_xor_sync(0xffffffffu, v, o);
                if ((tid & 31) == 0) atomicAdd(&qv[s][k], v);
            }
        }
        __syncthreads();
    }

    // ---- hidden: h = relu(q @ rW + rb) * gate_weight -> bf16 hi/lo ----
    #pragma unroll
    for (int s = 0; s < 2; s++) {
        int e = sel[s];
        float w = wsel[s];
        float qr[NQv];
        #pragma unroll
        for (int j = 0; j < NQv; j++) qr[j] = qv[s][j];
        const float* rWe = rW + ((size_t)(blk * EE + e)) * NQv * HHv;
        const float* rbe = rb + ((size_t)(blk * EE + e)) * HHv;
        size_t slot = (size_t)b * 2 + s;
        for (int n = tid; n < HHv; n += 256) {
            float a = rbe[n];
            #pragma unroll
            for (int j = 0; j < NQv; j++) a += qr[j] * rWe[j * HHv + n];
            float hv = fmaxf(a, 0.f) * w;
            __nv_bfloat16 hi = __float2bfloat16(hv);
            __nv_bfloat16 lo = __float2bfloat16(hv - __bfloat162float(hi));
            g_Hhi[slot * HHv + n] = hi;
            g_Hlo[slot * HHv + n] = lo;
        }
    }
}

// ---------------- grouped expert GEMM via mma.sync (bf16x3 split) ----------------
__global__ __launch_bounds__(256) void k_moe_gemm_mma(int blk)
{
    extern __shared__ char dsm[];
    __shared__ int rows[BM];

    int e = blockIdx.z;
    int n_e = g_cnt[e];
    int m0 = blockIdx.y * BM;
    if (m0 >= n_e) return;
    int n0 = blockIdx.x * BN;

    int tid = threadIdx.x;
    int lane = tid & 31;
    int wid = tid >> 5;
    int warp_m = wid >> 2;     // 0..1  -> 64 rows each
    int warp_n = wid & 3;      // 0..3  -> 32 cols each

    if (tid < BM) {
        int m = m0 + tid;
        rows[tid] = (m < n_e) ? g_list[e * BB + m] : -1;
    }
    __syncthreads();

    uint32_t sbase = smem_u32(dsm);
    const __nv_bfloat16* Bhi = g_w2Thi + (size_t)(blk * EE + e) * DD * HHv;
    const __nv_bfloat16* Blo = g_w2Tlo + (size_t)(blk * EE + e) * DD * HHv;

    // ---- async tile loader ----
    auto load_stage = [&](int chunk, int stage) {
        uint32_t sb = sbase + stage * STAGE_BYT;
        int kofs = chunk * BK;
        // A tiles (gathered rows, hi then lo)
        #pragma unroll
        for (int j = 0; j < 4; j++) {
            int idx = tid + 256 * j;       // 0..1023
            int row = idx >> 3;
            int seg = idx & 7;             // 16B segment of 128B row
            uint32_t doff = (uint32_t)(row * (APAD * 2) + seg * 16);
            int slot = rows[row];
            int sz = (slot >= 0) ? 16 : 0;
            size_t off = (size_t)(slot >= 0 ? slot : 0) * HHv + kofs + seg * 8;
            cp16z(sb + 0 * TILE_BYT + doff, g_Hhi + off, sz);
            cp16z(sb + 1 * TILE_BYT + doff, g_Hlo + off, sz);
        }
        // B tiles (w2^T rows n0..n0+127, hi then lo)
        #pragma unroll
        for (int j = 0; j < 4; j++) {
            int idx = tid + 256 * j;
            int row = idx >> 3;
            int seg = idx & 7;
            uint32_t doff = (uint32_t)(row * (APAD * 2) + seg * 16);
            size_t off = (size_t)(n0 + row) * HHv + kofs + seg * 8;
            cp16(sb + 2 * TILE_BYT + doff, Bhi + off);
            cp16(sb + 3 * TILE_BYT + doff, Blo + off);
        }
    };

    float acc[4][4][4];
    #pragma unroll
    for (int i = 0; i < 4; i++)
        #pragma unroll
        for (int j = 0; j < 4; j++)
            #pragma unroll
            for (int q = 0; q < 4; q++) acc[i][j][q] = 0.f;

    // ldmatrix lane addressing (byte offsets within a tile)
    uint32_t a_row = (uint32_t)(warp_m * 64 + (lane & 15));
    uint32_t a_colp = (uint32_t)((lane >> 4) * 16);
    uint32_t b_row = (uint32_t)(warp_n * 32 + (lane & 7) + ((lane >> 4) & 1) * 8);
    uint32_t b_colp = (uint32_t)(((lane >> 3) & 1) * 16);

    load_stage(0, 0);
    cp_commit();

    for (int i = 0; i < NCH; i++) {
        if (i + 1 < NCH) { load_stage(i + 1, (i + 1) & 1); cp_commit(); }
        if (i + 1 < NCH) asm volatile("cp.async.wait_group 1;" ::: "memory");
        else             asm volatile("cp.async.wait_group 0;" ::: "memory");
        __syncthreads();

        uint32_t sb = sbase + (i & 1) * STAGE_BYT;
        uint32_t sAhi = sb, sAlo = sb + TILE_BYT, sBhi = sb + 2 * TILE_BYT, sBlo = sb + 3 * TILE_BYT;

        #pragma unroll
        for (int kk = 0; kk < BK / 16; kk++) {
            uint32_t kbyte = (uint32_t)(kk * 32);
            uint32_t ah[4][4], al[4][4], bh[2][4], bl[2][4];

            // A hi fragments (4 m-groups)
            #pragma unroll
            for (int mg = 0; mg < 4; mg++)
                ldm4(ah[mg], sAhi + (a_row + mg * 16) * (APAD * 2) + kbyte + a_colp);
            // B hi fragments (2 groups of 16 n)
            #pragma unroll
            for (int ng = 0; ng < 2; ng++)
                ldm4(bh[ng], sBhi + (b_row + ng * 16) * (APAD * 2) + kbyte + b_colp);

            // pass 1: Ahi * Bhi
            #pragma unroll
            for (int mg = 0; mg < 4; mg++)
                #pragma unroll
                for (int nf = 0; nf < 4; nf++)
                    mma16816(acc[mg][nf], ah[mg], &bh[nf >> 1][(nf & 1) * 2]);

            // pass 2: Alo * Bhi
            #pragma unroll
            for (int mg = 0; mg < 4; mg++)
                ldm4(al[mg], sAlo + (a_row + mg * 16) * (APAD * 2) + kbyte + a_colp);
            #pragma unroll
            for (int mg = 0; mg < 4; mg++)
                #pragma unroll
                for (int nf = 0; nf < 4; nf++)
                    mma16816(acc[mg][nf], al[mg], &bh[nf >> 1][(nf & 1) * 2]);

            // pass 3: Ahi * Blo
            #pragma unroll
            for (int ng = 0; ng < 2; ng++)
                ldm4(bl[ng], sBlo + (b_row + ng * 16) * (APAD * 2) + kbyte + b_colp);
            #pragma unroll
            for (int mg = 0; mg < 4; mg++)
                #pragma unroll
                for (int nf = 0; nf < 4; nf++)
                    mma16816(acc[mg][nf], ah[mg], &bl[nf >> 1][(nf & 1) * 2]);
        }
        __syncthreads();
    }

    // ---- epilogue: per-slot non-atomic stores ----
    int mb = warp_m * 64 + (lane >> 2);
    int nb = n0 + warp_n * 32 + (lane & 3) * 2;
    #pragma unroll
    for (int mg = 0; mg < 4; mg++) {
        int r0 = mb + mg * 16;
        int r1 = r0 + 8;
        int s0 = rows[r0], s1 = rows[r1];
        #pragma unroll
        for (int nf = 0; nf < 4; nf++) {
            int n = nb + nf * 8;
            if (s0 >= 0) *(float2*)(g_Eout + (size_t)s0 * DD + n) = make_float2(acc[mg][nf][0], acc[mg][nf][1]);
            if (s1 >= 0) *(float2*)(g_Eout + (size_t)s1 * DD + n) = make_float2(acc[mg][nf][2], acc[mg][nf][3]);
        }
    }
}

// ---------------- layernorm (combines residual-init + both slot outputs) ----------------
__device__ __forceinline__ float blockReduceSum(float v, float* red)
{
    __syncthreads();
    int lane = threadIdx.x & 31;
    int w = threadIdx.x >> 5;
    #pragma unroll
    for (int o = 16; o > 0; o >>= 1) v += __shfl_xor_sync(0xffffffffu, v, o);
    if (lane == 0) red[w] = v;
    __syncthreads();
    float r = (lane < 8) ? red[lane] : 0.f;
    #pragma unroll
    for (int o = 4; o > 0; o >>= 1) r += __shfl_xor_sync(0xffffffffu, r, o);
    return r;
}

__global__ __launch_bounds__(256) void k_ln(
    const float* __restrict__ gam, const float* __restrict__ bet,
    float* __restrict__ Yext, int blk)
{
    __shared__ float red[32];
    __shared__ float bc[2];
    int b = blockIdx.x, tid = threadIdx.x;
    float* Y = (blk == 0) ? g_X1 : Yext;

    const float* y  = g_OUT  + (size_t)b * DD;
    const float* e0 = g_Eout + (size_t)(2 * b) * DD;
    const float* e1 = e0 + DD;
    float v[4];
    float s = 0.f;
    #pragma unroll
    for (int i = 0; i < 4; i++) {
        int n = tid + 256 * i;
        v[i] = y[n] + e0[n] + e1[n];
        s += v[i];
    }
    float tot = blockReduceSum(s, red);
    if (tid == 0) bc[0] = tot;
    __syncthreads();
    float mu = bc[0] * (1.f / 1024.f);

    float s2 = 0.f;
    #pragma unroll
    for (int i = 0; i < 4; i++) { float d = v[i] - mu; s2 += d * d; }
    float tot2 = blockReduceSum(s2, red);
    if (tid == 0) bc[1] = tot2;
    __syncthreads();
    float inv = 1.f / sqrtf(bc[1] * (1.f / 1024.f) + 1e-5f);

    #pragma unroll
    for (int i = 0; i < 4; i++) {
        int n = tid + 256 * i;
        Y[(size_t)b * DD + n] = (v[i] - mu) * inv * gam[blk * DD + n] + bet[blk * DD + n];
    }
}

// ---------------- launch ----------------
extern "C" void kernel_launch(void* const* d_in, const int* in_sizes, int n_in,
                              void* d_out, int out_size)
{
    (void)in_sizes; (void)n_in; (void)out_size;
    const float* x  = (const float*)d_in[0];
    const float* gW = (const float*)d_in[1];
    const float* gb = (const float*)d_in[2];
    const float* qp = (const float*)d_in[3];
    const float* rW = (const float*)d_in[4];
    const float* rb = (const float*)d_in[5];
    const float* w2 = (const float*)d_in[6];
    const float* b2 = (const float*)d_in[7];
    const float* lg = (const float*)d_in[8];
    const float* lb = (const float*)d_in[9];
    float* out = (float*)d_out;

    cudaFuncSetAttribute(k_moe_gemm_mma, cudaFuncAttributeMaxDynamicSharedMemorySize, GEMM_SMEM);

    // one-time per launch: transpose + bf16-split all expert w2 matrices
    k_w2t<<<dim3(DD / 32, HHv / 32, 2 * EE), 256>>>(w2);

    for (int blk = 0; blk < 2; blk++) {
        k_reset<<<1, 32>>>();
        k_gate_qsim<<<BB, 256>>>(x, gW, gb, qp, rW, rb, b2, blk);
        dim3 g2(DD / BN, BB / BM, EE);
        k_moe_gemm_mma<<<g2, 256, GEMM_SMEM>>>(blk);
        k_ln<<<BB, 256>>>(lg, lb, out, blk);
    }
}

// round 7
// speedup vs baseline: 2.5939x; 1.2776x over previous
#include <cuda_runtime.h>
#include <cuda_bf16.h>
#include <cstdint>
#include <math.h>

#define BB 8192
#define DD 1024
#define EE 8
#define NQv 8
#define NLv 2
#define HHv 1024

// ---------------- scratch (static device globals: no allocation) ----------------
__device__ float g_X1[(size_t)BB * DD];                 // inter-block activations
__device__ __nv_bfloat16 g_Hhi[(size_t)BB * 2 * HHv];   // hidden, bf16 hi
__device__ __nv_bfloat16 g_Hlo[(size_t)BB * 2 * HHv];   // hidden, bf16 lo
__device__ float g_OUT[(size_t)BB * DD];                // residual + expert biases
__device__ float g_Eout[(size_t)BB * 2 * DD];           // per-slot GEMM output
__device__ __nv_bfloat16 g_w2Thi[(size_t)2 * EE * DD * HHv]; // w2^T [e][n][k] hi
__device__ __nv_bfloat16 g_w2Tlo[(size_t)2 * EE * DD * HHv]; // w2^T [e][n][k] lo
__device__ int   g_cnt[EE];
__device__ int   g_list[EE * BB];                       // entries encode row*2+slot

// ---------------- generic PTX helpers ----------------
static __device__ __forceinline__ uint32_t smem_u32(const void* p) {
    uint32_t a;
    asm("{ .reg .u64 t; cvta.to.shared.u64 t, %1; cvt.u32.u64 %0, t; }" : "=r"(a) : "l"(p));
    return a;
}
static __device__ __forceinline__ void cp16(uint32_t dst, const void* src) {
    asm volatile("cp.async.cg.shared.global [%0], [%1], 16;" :: "r"(dst), "l"(src) : "memory");
}
static __device__ __forceinline__ void cp16z(uint32_t dst, const void* src, int srcsize) {
    asm volatile("cp.async.cg.shared.global [%0], [%1], 16, %2;" :: "r"(dst), "l"(src), "r"(srcsize) : "memory");
}
static __device__ __forceinline__ void cp_commit() {
    asm volatile("cp.async.commit_group;" ::: "memory");
}
static __device__ __forceinline__ void ldm4(uint32_t* r, uint32_t addr) {
    asm volatile("ldmatrix.sync.aligned.m8n8.x4.shared.b16 {%0,%1,%2,%3}, [%4];"
        : "=r"(r[0]), "=r"(r[1]), "=r"(r[2]), "=r"(r[3]) : "r"(addr));
}
static __device__ __forceinline__ void mma16816(float* c, const uint32_t* a, const uint32_t* b) {
    asm volatile("mma.sync.aligned.m16n8k16.row.col.f32.bf16.bf16.f32 "
        "{%0,%1,%2,%3}, {%4,%5,%6,%7}, {%8,%9}, {%0,%1,%2,%3};"
        : "+f"(c[0]), "+f"(c[1]), "+f"(c[2]), "+f"(c[3])
        : "r"(a[0]), "r"(a[1]), "r"(a[2]), "r"(a[3]), "r"(b[0]), "r"(b[1]));
}

// ---------------- GEMM tile config (BK=32, 2-stage, 2 CTA/SM) ----------------
#define BM 128
#define BN 128
#define BK 32
#define NCH (HHv / BK)                 // 32
#define RSTR 80                         // bytes per SMEM row (16B-aligned, conflict-free)
#define TILE_BYT (BM * RSTR)            // 10240
#define STAGE_BYT (4 * TILE_BYT)        // 40960: Ahi, Alo, Bhi, Blo
#define GEMM_SMEM (2 * STAGE_BYT)       // 81920

// ---------------- reset ----------------
__global__ void k_reset() {
    if (threadIdx.x < EE) g_cnt[threadIdx.x] = 0;
}

// ---------------- w2 -> w2^T, split fp32 into bf16 hi/lo ----------------
__global__ __launch_bounds__(256) void k_w2t(const float* __restrict__ w2)
{
    __shared__ float tile[32][33];
    int ez = blockIdx.z;
    int k0 = blockIdx.y * 32;
    int n0 = blockIdx.x * 32;
    int tx = threadIdx.x & 31, ty = threadIdx.x >> 5;

    const float* src = w2 + (size_t)ez * HHv * DD;
    #pragma unroll
    for (int r = 0; r < 32; r += 8)
        tile[ty + r][tx] = src[(size_t)(k0 + ty + r) * DD + n0 + tx];
    __syncthreads();

    __nv_bfloat16* dhi = g_w2Thi + (size_t)ez * DD * HHv;
    __nv_bfloat16* dlo = g_w2Tlo + (size_t)ez * DD * HHv;
    #pragma unroll
    for (int r = 0; r < 32; r += 8) {
        float v = tile[tx][ty + r];
        __nv_bfloat16 hi = __float2bfloat16(v);
        __nv_bfloat16 lo = __float2bfloat16(v - __bfloat162float(hi));
        size_t o = (size_t)(n0 + ty + r) * HHv + k0 + tx;
        dhi[o] = hi; dlo[o] = lo;
    }
}

// ---------------- warp-resident gate + qsim + hidden (1 warp per row) ----------------
__global__ __launch_bounds__(256) void k_gate_qsim_w(
    const float* __restrict__ Xext,
    const float* __restrict__ gW, const float* __restrict__ gb,
    const float* __restrict__ qp, const float* __restrict__ rW,
    const float* __restrict__ rb, const float* __restrict__ b2,
    int blk)
{
    __shared__ float2 stbuf[8][256];     // per-warp CNOT permute buffer
    const unsigned FULL = 0xffffffffu;
    int wid = threadIdx.x >> 5;
    int lane = threadIdx.x & 31;
    int b = blockIdx.x * 8 + wid;

    const float* X = (blk == 0) ? Xext : g_X1;
    const float4* xr4 = (const float4*)(X + (size_t)b * DD);

    // ---- load x row: lane holds elements (j*32+lane)*4 .. +3 ----
    float4 xv[8];
    #pragma unroll
    for (int j = 0; j < 8; j++) xv[j] = xr4[j * 32 + lane];

    // ---- gate logits ----
    float acc[EE];
    #pragma unroll
    for (int e = 0; e < EE; e++) acc[e] = 0.f;
    const float* gwb = gW + (size_t)blk * DD * EE;
    #pragma unroll
    for (int j = 0; j < 8; j++) {
        int d0 = (j * 32 + lane) * 4;
        const float xs[4] = { xv[j].x, xv[j].y, xv[j].z, xv[j].w };
        #pragma unroll
        for (int c = 0; c < 4; c++) {
            const float4* gr = (const float4*)(gwb + (size_t)(d0 + c) * EE);
            float4 g0 = gr[0], g1 = gr[1];
            float xvv = xs[c];
            acc[0] += xvv * g0.x; acc[1] += xvv * g0.y; acc[2] += xvv * g0.z; acc[3] += xvv * g0.w;
            acc[4] += xvv * g1.x; acc[5] += xvv * g1.y; acc[6] += xvv * g1.z; acc[7] += xvv * g1.w;
        }
    }
    #pragma unroll
    for (int e = 0; e < EE; e++) {
        #pragma unroll
        for (int o = 16; o > 0; o >>= 1) acc[e] += __shfl_xor_sync(FULL, acc[e], o);
    }

    // ---- softmax + top2 (computed redundantly on all lanes) ----
    float l[EE], mx = -1e30f;
    #pragma unroll
    for (int e = 0; e < EE; e++) { l[e] = acc[e] + gb[blk * EE + e]; mx = fmaxf(mx, l[e]); }
    float sum = 0.f;
    #pragma unroll
    for (int e = 0; e < EE; e++) { l[e] = expf(l[e] - mx); sum += l[e]; }
    float inv = 1.f / sum;
    #pragma unroll
    for (int e = 0; e < EE; e++) l[e] *= inv;
    int i0 = 0;
    #pragma unroll
    for (int e = 1; e < EE; e++) if (l[e] > l[i0]) i0 = e;
    int i1 = (i0 == 0) ? 1 : 0;
    #pragma unroll
    for (int e = 0; e < EE; e++) if (e != i1 && e != i0 && l[e] > l[i1]) i1 = e;
    float p0 = l[i0], p1 = l[i1];
    float w1 = 1.f / (1.f + expf(p0 - p1));
    float w0 = 1.f - w1;
    if (lane == 0) {
        int pos0 = atomicAdd(&g_cnt[i0], 1); g_list[i0 * BB + pos0] = b * 2 + 0;
        int pos1 = atomicAdd(&g_cnt[i1], 1); g_list[i1 * BB + pos1] = b * 2 + 1;
    }

    // ---- residual + weighted expert biases -> g_OUT ----
    {
        const float4* b2a = (const float4*)(b2 + ((size_t)blk * EE + i0) * DD);
        const float4* b2b = (const float4*)(b2 + ((size_t)blk * EE + i1) * DD);
        float4* outp = (float4*)(g_OUT + (size_t)b * DD);
        #pragma unroll
        for (int j = 0; j < 8; j++) {
            float4 ba = b2a[j * 32 + lane], bbv = b2b[j * 32 + lane];
            float4 o;
            o.x = xv[j].x + w0 * ba.x + w1 * bbv.x;
            o.y = xv[j].y + w0 * ba.y + w1 * bbv.y;
            o.z = xv[j].z + w0 * ba.z + w1 * bbv.z;
            o.w = xv[j].w + w0 * ba.w + w1 * bbv.w;
            outp[j * 32 + lane] = o;
        }
    }

    // ---- per-qubit angle cos/sin, broadcast to all lanes ----
    // x[q] for q=0..7 lives in xv[0] of lanes 0 (comps 0-3) and 1 (comps 4-7)
    float v0 = __shfl_sync(FULL, xv[0].x, lane >> 2);
    float v1 = __shfl_sync(FULL, xv[0].y, lane >> 2);
    float v2 = __shfl_sync(FULL, xv[0].z, lane >> 2);
    float v3 = __shfl_sync(FULL, xv[0].w, lane >> 2);
    float xq = (lane & 2) ? ((lane & 1) ? v3 : v2) : ((lane & 1) ? v1 : v0);
    float cq_own, sq_own;
    sincosf(0.5f * xq, &sq_own, &cq_own);
    float cqv[NQv], sqv[NQv];
    #pragma unroll
    for (int q = 0; q < NQv; q++) {
        cqv[q] = __shfl_sync(FULL, cq_own, q);
        sqv[q] = __shfl_sync(FULL, sq_own, q);
    }

    int esel[2] = { i0, i1 };
    float wsel[2] = { w0, w1 };
    float2* sw = stbuf[wid];

    #pragma unroll
    for (int s = 0; s < 2; s++) {
        int e = esel[s];

        // ---- initial product state: lane holds idx = lane*8 + j ----
        float2 st[8];
        #pragma unroll
        for (int j = 0; j < 8; j++) {
            int idx = lane * 8 + j;
            float v = 1.f;
            #pragma unroll
            for (int q = 0; q < NQv; q++)
                v *= ((idx >> (NQv - 1 - q)) & 1) ? sqv[q] : cqv[q];
            st[j] = make_float2(v, 0.f);
        }

        const float* qpe = qp + (size_t)(blk * EE + e) * NLv * NQv * 3;
        #pragma unroll
        for (int lyr = 0; lyr < NLv; lyr++) {
            // rot matrices: lane (&7) computes qubit lane's 2x2 complex matrix
            const float* pp = qpe + (lyr * NQv + (lane & 7)) * 3;
            float phi = pp[0], th = pp[1], om = pp[2];
            float c, sn; sincosf(0.5f * th, &sn, &c);
            float sa, ca; sincosf(0.5f * (phi + om), &sa, &ca);
            float sb, cb; sincosf(0.5f * (phi - om), &sb, &cb);
            float o00r = ca * c,  o00i = -sa * c;
            float o11r = ca * c,  o11i =  sa * c;
            float o01r = -cb * sn, o01i = -sb * sn;
            float o10r =  cb * sn, o10i = -sb * sn;

            #pragma unroll
            for (int q = 0; q < NQv; q++) {
                float M00r = __shfl_sync(FULL, o00r, q), M00i = __shfl_sync(FULL, o00i, q);
                float M01r = __shfl_sync(FULL, o01r, q), M01i = __shfl_sync(FULL, o01i, q);
                float M10r = __shfl_sync(FULL, o10r, q), M10i = __shfl_sync(FULL, o10i, q);
                float M11r = __shfl_sync(FULL, o11r, q), M11i = __shfl_sync(FULL, o11i, q);
                const int pb = NQv - 1 - q;
                if (pb >= 3) {
                    int msk = 1 << (pb - 3);
                    int bit = (lane >> (pb - 3)) & 1;
                    float Msr = bit ? M11r : M00r, Msi = bit ? M11i : M00i;
                    float Mpr = bit ? M10r : M01r, Mpi = bit ? M10i : M01i;
                    #pragma unroll
                    for (int j = 0; j < 8; j++) {
                        float px = __shfl_xor_sync(FULL, st[j].x, msk);
                        float py = __shfl_xor_sync(FULL, st[j].y, msk);
                        float nx = Msr * st[j].x - Msi * st[j].y + Mpr * px - Mpi * py;
                        float ny = Msr * st[j].y + Msi * st[j].x + Mpr * py + Mpi * px;
                        st[j] = make_float2(nx, ny);
                    }
                } else {
                    const int m = 1 << pb;
                    #pragma unroll
                    for (int j = 0; j < 8; j++) {
                        if (!(j & m)) {
                            float2 a0 = st[j], a1 = st[j | m];
                            float2 n0, n1;
                            n0.x = M00r * a0.x - M00i * a0.y + M01r * a1.x - M01i * a1.y;
                            n0.y = M00r * a0.y + M00i * a0.x + M01r * a1.y + M01i * a1.x;
                            n1.x = M10r * a0.x - M10i * a0.y + M11r * a1.x - M11i * a1.y;
                            n1.y = M10r * a0.y + M10i * a0.x + M11r * a1.y + M11i * a1.x;
                            st[j] = n0; st[j | m] = n1;
                        }
                    }
                }
            }
            // CNOT chain permutation via warp-private smem
            #pragma unroll
            for (int j = 0; j < 8; j++) sw[lane * 8 + j] = st[j];
            __syncwarp();
            #pragma unroll
            for (int j = 0; j < 8; j++) {
                int idx = lane * 8 + j;
                int jsrc = idx;
                #pragma unroll
                for (int q = NQv - 2; q >= 0; q--) {
                    int pc = NQv - 1 - q, pt = NQv - 2 - q;
                    jsrc ^= ((jsrc >> pc) & 1) << pt;
                }
                st[j] = sw[jsrc];
            }
            __syncwarp();
        }

        // ---- Z expectations ----
        float zp[NQv];
        #pragma unroll
        for (int k = 0; k < NQv; k++) zp[k] = 0.f;
        #pragma unroll
        for (int j = 0; j < 8; j++) {
            int idx = lane * 8 + j;
            float p = st[j].x * st[j].x + st[j].y * st[j].y;
            #pragma unroll
            for (int k = 0; k < NQv; k++)
                zp[k] += ((idx >> (NQv - 1 - k)) & 1) ? -p : p;
        }
        #pragma unroll
        for (int k = 0; k < NQv; k++) {
            #pragma unroll
            for (int o = 16; o > 0; o >>= 1) zp[k] += __shfl_xor_sync(FULL, zp[k], o);
        }

        // ---- hidden: h = relu(q @ rW + rb) * gate_w -> bf16 hi/lo ----
        float wgt = wsel[s];
        const float* rWe = rW + (size_t)(blk * EE + e) * NQv * HHv;
        const float4* rbe = (const float4*)(rb + (size_t)(blk * EE + e) * HHv);
        size_t slot = (size_t)b * 2 + s;
        uint2* dhi = (uint2*)(g_Hhi + slot * HHv);
        uint2* dlo = (uint2*)(g_Hlo + slot * HHv);
        #pragma unroll
        for (int j = 0; j < 8; j++) {
            int g = j * 32 + lane;
            float4 a = rbe[g];
            #pragma unroll
            for (int jj = 0; jj < NQv; jj++) {
                float4 wv = ((const float4*)(rWe + (size_t)jj * HHv))[g];
                a.x += zp[jj] * wv.x; a.y += zp[jj] * wv.y;
                a.z += zp[jj] * wv.z; a.w += zp[jj] * wv.w;
            }
            a.x = fmaxf(a.x, 0.f) * wgt; a.y = fmaxf(a.y, 0.f) * wgt;
            a.z = fmaxf(a.z, 0.f) * wgt; a.w = fmaxf(a.w, 0.f) * wgt;
            __nv_bfloat16 hx = __float2bfloat16(a.x), hy = __float2bfloat16(a.y);
            __nv_bfloat16 hz = __float2bfloat16(a.z), hw = __float2bfloat16(a.w);
            __nv_bfloat16 lx = __float2bfloat16(a.x - __bfloat162float(hx));
            __nv_bfloat16 ly = __float2bfloat16(a.y - __bfloat162float(hy));
            __nv_bfloat16 lz = __float2bfloat16(a.z - __bfloat162float(hz));
            __nv_bfloat16 lw = __float2bfloat16(a.w - __bfloat162float(hw));
            uint2 uh, ul;
            uh.x = ((uint32_t)__bfloat16_as_ushort(hy) << 16) | __bfloat16_as_ushort(hx);
            uh.y = ((uint32_t)__bfloat16_as_ushort(hw) << 16) | __bfloat16_as_ushort(hz);
            ul.x = ((uint32_t)__bfloat16_as_ushort(ly) << 16) | __bfloat16_as_ushort(lx);
            ul.y = ((uint32_t)__bfloat16_as_ushort(lw) << 16) | __bfloat16_as_ushort(lz);
            dhi[g] = uh;
            dlo[g] = ul;
        }
    }
}

// ---------------- grouped expert GEMM via mma.sync (bf16x3 split) ----------------
__global__ __launch_bounds__(256, 2) void k_moe_gemm_mma(int blk)
{
    extern __shared__ char dsm[];
    __shared__ int rows[BM];

    int e = blockIdx.z;
    int n_e = g_cnt[e];
    int m0 = blockIdx.y * BM;
    if (m0 >= n_e) return;
    int n0 = blockIdx.x * BN;

    int tid = threadIdx.x;
    int lane = tid & 31;
    int wid = tid >> 5;
    int warp_m = wid >> 2;     // 0..1  -> 64 rows each
    int warp_n = wid & 3;      // 0..3  -> 32 cols each

    if (tid < BM) {
        int m = m0 + tid;
        rows[tid] = (m < n_e) ? g_list[e * BB + m] : -1;
    }
    __syncthreads();

    uint32_t sbase = smem_u32(dsm);
    const __nv_bfloat16* Bhi = g_w2Thi + (size_t)(blk * EE + e) * DD * HHv;
    const __nv_bfloat16* Blo = g_w2Tlo + (size_t)(blk * EE + e) * DD * HHv;

    // ---- async tile loader (BK=32: 4 x 16B segments per 64B row) ----
    auto load_stage = [&](int chunk, int stage) {
        uint32_t sb = sbase + stage * STAGE_BYT;
        int kofs = chunk * BK;
        #pragma unroll
        for (int j = 0; j < 2; j++) {
            int idx = tid + 256 * j;       // 0..511
            int row = idx >> 2;
            int seg = idx & 3;
            uint32_t doff = (uint32_t)(row * RSTR + seg * 16);
            int slot = rows[row];
            int sz = (slot >= 0) ? 16 : 0;
            size_t off = (size_t)(slot >= 0 ? slot : 0) * HHv + kofs + seg * 8;
            cp16z(sb + 0 * TILE_BYT + doff, g_Hhi + off, sz);
            cp16z(sb + 1 * TILE_BYT + doff, g_Hlo + off, sz);
            size_t boff = (size_t)(n0 + row) * HHv + kofs + seg * 8;
            cp16(sb + 2 * TILE_BYT + doff, Bhi + boff);
            cp16(sb + 3 * TILE_BYT + doff, Blo + boff);
        }
    };

    float acc[4][4][4];
    #pragma unroll
    for (int i = 0; i < 4; i++)
        #pragma unroll
        for (int j = 0; j < 4; j++)
            #pragma unroll
            for (int q = 0; q < 4; q++) acc[i][j][q] = 0.f;

    uint32_t a_row = (uint32_t)(warp_m * 64 + (lane & 15));
    uint32_t a_colp = (uint32_t)((lane >> 4) * 16);
    uint32_t b_row = (uint32_t)(warp_n * 32 + (lane & 7) + ((lane >> 4) & 1) * 8);
    uint32_t b_colp = (uint32_t)(((lane >> 3) & 1) * 16);

    load_stage(0, 0);
    cp_commit();

    for (int i = 0; i < NCH; i++) {
        if (i + 1 < NCH) { load_stage(i + 1, (i + 1) & 1); cp_commit(); }
        if (i + 1 < NCH) asm volatile("cp.async.wait_group 1;" ::: "memory");
        else             asm volatile("cp.async.wait_group 0;" ::: "memory");
        __syncthreads();

        uint32_t sb = sbase + (i & 1) * STAGE_BYT;
        uint32_t sAhi = sb, sAlo = sb + TILE_BYT, sBhi = sb + 2 * TILE_BYT, sBlo = sb + 3 * TILE_BYT;

        #pragma unroll
        for (int kk = 0; kk < BK / 16; kk++) {
            uint32_t kbyte = (uint32_t)(kk * 32);
            uint32_t ah[4][4], al[4][4], bh[2][4], bl[2][4];

            #pragma unroll
            for (int mg = 0; mg < 4; mg++)
                ldm4(ah[mg], sAhi + (a_row + mg * 16) * RSTR + kbyte + a_colp);
            #pragma unroll
            for (int ng = 0; ng < 2; ng++)
                ldm4(bh[ng], sBhi + (b_row + ng * 16) * RSTR + kbyte + b_colp);
            #pragma unroll
            for (int ng = 0; ng < 2; ng++)
                ldm4(bl[ng], sBlo + (b_row + ng * 16) * RSTR + kbyte + b_colp);

            // pass 1: Ahi * Bhi
            #pragma unroll
            for (int mg = 0; mg < 4; mg++)
                #pragma unroll
                for (int nf = 0; nf < 4; nf++)
                    mma16816(acc[mg][nf], ah[mg], &bh[nf >> 1][(nf & 1) * 2]);
            // pass 2: Ahi * Blo (ah then dead)
            #pragma unroll
            for (int mg = 0; mg < 4; mg++)
                #pragma unroll
                for (int nf = 0; nf < 4; nf++)
                    mma16816(acc[mg][nf], ah[mg], &bl[nf >> 1][(nf & 1) * 2]);
            // pass 3: Alo * Bhi
            #pragma unroll
            for (int mg = 0; mg < 4; mg++)
                ldm4(al[mg], sAlo + (a_row + mg * 16) * RSTR + kbyte + a_colp);
            #pragma unroll
            for (int mg = 0; mg < 4; mg++)
                #pragma unroll
                for (int nf = 0; nf < 4; nf++)
                    mma16816(acc[mg][nf], al[mg], &bh[nf >> 1][(nf & 1) * 2]);
        }
        __syncthreads();
    }

    // ---- epilogue: per-slot non-atomic stores ----
    int mb = warp_m * 64 + (lane >> 2);
    int nb = n0 + warp_n * 32 + (lane & 3) * 2;
    #pragma unroll
    for (int mg = 0; mg < 4; mg++) {
        int r0 = mb + mg * 16;
        int r1 = r0 + 8;
        int s0 = rows[r0], s1 = rows[r1];
        #pragma unroll
        for (int nf = 0; nf < 4; nf++) {
            int n = nb + nf * 8;
            if (s0 >= 0) *(float2*)(g_Eout + (size_t)s0 * DD + n) = make_float2(acc[mg][nf][0], acc[mg][nf][1]);
            if (s1 >= 0) *(float2*)(g_Eout + (size_t)s1 * DD + n) = make_float2(acc[mg][nf][2], acc[mg][nf][3]);
        }
    }
}

// ---------------- layernorm (combines residual-init + both slot outputs) ----------------
__device__ __forceinline__ float blockReduceSum(float v, float* red)
{
    __syncthreads();
    int lane = threadIdx.x & 31;
    int w = threadIdx.x >> 5;
    #pragma unroll
    for (int o = 16; o > 0; o >>= 1) v += __shfl_xor_sync(0xffffffffu, v, o);
    if (lane == 0) red[w] = v;
    __syncthreads();
    float r = (lane < 8) ? red[lane] : 0.f;
    #pragma unroll
    for (int o = 4; o > 0; o >>= 1) r += __shfl_xor_sync(0xffffffffu, r, o);
    return r;
}

__global__ __launch_bounds__(256) void k_ln(
    const float* __restrict__ gam, const float* __restrict__ bet,
    float* __restrict__ Yext, int blk)
{
    __shared__ float red[32];
    __shared__ float bc[2];
    int b = blockIdx.x, tid = threadIdx.x;
    float* Y = (blk == 0) ? g_X1 : Yext;

    const float* y  = g_OUT  + (size_t)b * DD;
    const float* e0 = g_Eout + (size_t)(2 * b) * DD;
    const float* e1 = e0 + DD;
    float v[4];
    float s = 0.f;
    #pragma unroll
    for (int i = 0; i < 4; i++) {
        int n = tid + 256 * i;
        v[i] = y[n] + e0[n] + e1[n];
        s += v[i];
    }
    float tot = blockReduceSum(s, red);
    if (tid == 0) bc[0] = tot;
    __syncthreads();
    float mu = bc[0] * (1.f / 1024.f);

    float s2 = 0.f;
    #pragma unroll
    for (int i = 0; i < 4; i++) { float d = v[i] - mu; s2 += d * d; }
    float tot2 = blockReduceSum(s2, red);
    if (tid == 0) bc[1] = tot2;
    __syncthreads();
    float inv = 1.f / sqrtf(bc[1] * (1.f / 1024.f) + 1e-5f);

    #pragma unroll
    for (int i = 0; i < 4; i++) {
        int n = tid + 256 * i;
        Y[(size_t)b * DD + n] = (v[i] - mu) * inv * gam[blk * DD + n] + bet[blk * DD + n];
    }
}

// ---------------- launch ----------------
extern "C" void kernel_launch(void* const* d_in, const int* in_sizes, int n_in,
                              void* d_out, int out_size)
{
    (void)in_sizes; (void)n_in; (void)out_size;
    const float* x  = (const float*)d_in[0];
    const float* gW = (const float*)d_in[1];
    const float* gb = (const float*)d_in[2];
    const float* qp = (const float*)d_in[3];
    const float* rW = (const float*)d_in[4];
    const float* rb = (const float*)d_in[5];
    const float* w2 = (const float*)d_in[6];
    const float* b2 = (const float*)d_in[7];
    const float* lg = (const float*)d_in[8];
    const float* lb = (const float*)d_in[9];
    float* out = (float*)d_out;

    cudaFuncSetAttribute(k_moe_gemm_mma, cudaFuncAttributeMaxDynamicSharedMemorySize, GEMM_SMEM);

    // one-time per launch: transpose + bf16-split all expert w2 matrices
    k_w2t<<<dim3(DD / 32, HHv / 32, 2 * EE), 256>>>(w2);

    for (int blk = 0; blk < 2; blk++) {
        k_reset<<<1, 32>>>();
        k_gate_qsim_w<<<BB / 8, 256>>>(x, gW, gb, qp, rW, rb, b2, blk);
        dim3 g2(DD / BN, BB / BM, EE);
        k_moe_gemm_mma<<<g2, 256, GEMM_SMEM>>>(blk);
        k_ln<<<BB, 256>>>(lg, lb, out, blk);
    }
}